// round 15
// baseline (speedup 1.0000x reference)
#include <cuda_runtime.h>

#define S 14
#define NT 352
#define NSTEPS 32

typedef unsigned long long ull;

__device__ __forceinline__ ull pk2(float lo, float hi) {
    ull r; asm("mov.b64 %0,{%1,%2};" : "=l"(r) : "f"(lo), "f"(hi)); return r;
}
__device__ __forceinline__ void upk2(ull v, float& lo, float& hi) {
    asm("mov.b64 {%0,%1},%2;" : "=f"(lo), "=f"(hi) : "l"(v));
}
__device__ __forceinline__ void fma2(ull& d, ull a, ull b) {
    asm("fma.rn.f32x2 %0,%1,%2,%3;" : "=l"(d) : "l"(a), "l"(b), "l"(d));
}
// replicate one-bit -> {1.0f,1.0f} or {0,0} packed, no I2F
__device__ __forceinline__ ull bit2f2(unsigned m, int ci) {
    unsigned fb = ((m >> ci) & 1u) * 0x3f800000u;
    ull r; asm("mov.b64 %0,{%1,%1};" : "=l"(r) : "r"(fb)); return r;
}

// phase-2 scheduling: 14*98 = 1372 full items -> 1336 full + 72 halves = 1408 = 4*NT
#define P2_FULL 1336
#define P2_SCHED 1408

struct __align__(16) Smem {
    char uA[50432];              // xp[S][900] (ph0-1) | spkw[S][104] @0 | Y[S*10][33] @8192
    unsigned p1m[S][256];        // 16x16 padded, 10-bit channel mask
    ull w1p[45];                 // conv1 weights, channel pairs
    __align__(16) ull w2p[1080]; // conv2 weights [half][ci][k][6] (pad q=5 -> 0)
    __align__(16) ull wf2p[100][6];  // fc2 weights, o-pairs (pad [5]=0)
    unsigned zTm[32 * S];        // [lane][s]: bit k = z[k*32+lane] of sample s
    float hs[S][100];
    float cnts[S][10];
};

__global__ __launch_bounds__(NT, 2) void snn_fused_kernel(
    const float* __restrict__ x,    // [B,1,28,28]
    const float* __restrict__ Wc1,  // [10,1,3,3]
    const float* __restrict__ Wc2,  // [20,10,3,3]
    const float* __restrict__ Wf1,  // [100,980]
    const float* __restrict__ Wf2,  // [10,100]
    float* __restrict__ out,        // [B,10]
    int B)
{
    extern __shared__ __align__(16) char smem_raw[];
    Smem* sm = (Smem*)smem_raw;

    float*    xp   = (float*)sm->uA;              // [S][900]   (ph0-1)
    unsigned* spkw = (unsigned*)sm->uA;           // [S][104]   (stage A+)
    float*    Y    = (float*)(sm->uA + 8192);     // [S*10][33] (stage B+)
    unsigned* zT   = sm->zTm;

    const int t  = threadIdx.x;
    const int b0 = blockIdx.x * S;
    const int warp = t >> 5, lane = t & 31;

    // ---- init ----
    for (int i = t; i < S * 900; i += NT) xp[i] = 0.f;
    for (int i = t; i < 32 * S; i += NT) zT[i] = 0u;
    for (int i = t; i < S * 256; i += NT) ((unsigned*)sm->p1m)[i] = 0u;
    for (int i = t; i < 45; i += NT) {
        int cp = i / 9, k = i - cp * 9;
        sm->w1p[i] = pk2(Wc1[(2 * cp) * 9 + k], Wc1[(2 * cp + 1) * 9 + k]);
    }
    for (int i = t; i < 1080; i += NT) {
        int q6 = i % 6, k = (i / 6) % 9, ci = (i / 54) % 10, half = i / 540;
        if (q6 < 5) {
            int cA = half * 10 + 2 * q6;
            sm->w2p[i] = pk2(Wc2[cA * 90 + ci * 9 + k], Wc2[(cA + 1) * 90 + ci * 9 + k]);
        } else sm->w2p[i] = 0ULL;
    }
    for (int i = t; i < 600; i += NT) {
        int ii = i / 6, q = i - (i / 6) * 6;
        sm->wf2p[ii][q] = (q < 5) ? pk2(Wf2[(2 * q) * 100 + ii], Wf2[(2 * q + 1) * 100 + ii]) : 0ULL;
    }
    __syncthreads();

    // ---- stage inputs (float4: 28 floats/row = 7 float4, rows never split) ----
    for (int i = t; i < S * 196; i += NT) {
        int s = i / 196, j4 = i - s * 196;
        if (b0 + s < B) {
            int y = j4 / 7, c4 = (j4 - y * 7) * 4;
            float4 v = ((const float4*)(x + (size_t)(b0 + s) * 784))[j4];
            float* dst = &xp[s * 900 + (y + 1) * 30 + (c4 + 1)];
            dst[0] = v.x; dst[1] = v.y; dst[2] = v.z; dst[3] = v.w;
        }
    }
    __syncthreads();

    // ---- phase 1: conv1(1->10)+spike+pool, f32x2 over 5 channel pairs ----
    for (int idx = t; idx < S * 196; idx += NT) {
        int s   = idx / 196;
        int pos = idx - s * 196;
        int py = pos / 14, px = pos - py * 14;

        ull rr[4][4];
        {
            int base = s * 900 + (2 * py) * 30 + 2 * px;   // even -> 8B aligned
            #pragma unroll
            for (int dy = 0; dy < 4; dy++) {
                float2 a  = *(const float2*)&xp[base + dy * 30];
                float2 bq = *(const float2*)&xp[base + dy * 30 + 2];
                rr[dy][0] = pk2(a.x, a.x);  rr[dy][1] = pk2(a.y, a.y);
                rr[dy][2] = pk2(bq.x, bq.x); rr[dy][3] = pk2(bq.y, bq.y);
            }
        }
        ull acc[5][4];
        #pragma unroll
        for (int q = 0; q < 5; q++)
            #pragma unroll
            for (int p = 0; p < 4; p++) acc[q][p] = 0ULL;

        #pragma unroll
        for (int ky = 0; ky < 3; ky++)
        #pragma unroll
        for (int kx = 0; kx < 3; kx++) {
            int k = ky * 3 + kx;
            #pragma unroll
            for (int q = 0; q < 5; q++) {
                ull wp = sm->w1p[q * 9 + k];
                fma2(acc[q][0], rr[ky  ][kx  ], wp);
                fma2(acc[q][1], rr[ky  ][kx+1], wp);
                fma2(acc[q][2], rr[ky+1][kx  ], wp);
                fma2(acc[q][3], rr[ky+1][kx+1], wp);
            }
        }
        unsigned mask = 0u;
        #pragma unroll
        for (int q = 0; q < 5; q++) {
            float a0,b0v,a1,b1v,a2,b2v,a3,b3v;
            upk2(acc[q][0], a0, b0v); upk2(acc[q][1], a1, b1v);
            upk2(acc[q][2], a2, b2v); upk2(acc[q][3], a3, b3v);
            float mA = fmaxf(fmaxf(a0, a1), fmaxf(a2, a3));
            float mB = fmaxf(fmaxf(b0v, b1v), fmaxf(b2v, b3v));
            if (mA >= 1.0f) mask |= (1u << (2 * q));
            if (mB >= 1.0f) mask |= (1u << (2 * q + 1));
        }
        sm->p1m[s][(py + 1) * 16 + (px + 1)] = mask;
    }
    __syncthreads();

    // ---- phase 2: conv2(10->20)+spike+pool -> z bits into zT ----
    // 1408 = 4*NT scheduled: idx<P2_FULL full (2x2 window); rest half-items
    // (one pool row each; halves OR into the same z bit — max == OR of fires)
    for (int idx = t; idx < P2_SCHED; idx += NT) {
        int orig, sub;
        if (idx < P2_FULL) { orig = idx; sub = -1; }
        else { int j = idx - P2_FULL; orig = P2_FULL + (j >> 1); sub = j & 1; }
        int s    = orig / 98;
        int rem  = orig - s * 98;
        int half = rem / 49;
        int pos  = rem - half * 49;
        int py = pos / 7, px = pos - py * 7;

        if (sub < 0) {
            // ---- full item: 4 conv positions ----
            unsigned m[4][4];
            int base = (2 * py) * 16 + 2 * px;
            #pragma unroll
            for (int dy = 0; dy < 4; dy++) {
                const unsigned* pp = &sm->p1m[s][base + dy * 16];
                uint2 a  = *(const uint2*)&pp[0];
                uint2 bq = *(const uint2*)&pp[2];
                m[dy][0] = a.x; m[dy][1] = a.y; m[dy][2] = bq.x; m[dy][3] = bq.y;
            }
            ull acc[5][4];
            #pragma unroll
            for (int q = 0; q < 5; q++)
                #pragma unroll
                for (int p = 0; p < 4; p++) acc[q][p] = 0ULL;

            #pragma unroll 1
            for (int ci = 0; ci < 10; ci++) {
                ull rr[4][4];
                #pragma unroll
                for (int dy = 0; dy < 4; dy++)
                #pragma unroll
                for (int dx = 0; dx < 4; dx++)
                    rr[dy][dx] = bit2f2(m[dy][dx], ci);
                const ull* wb = &sm->w2p[(half * 10 + ci) * 54];
                #pragma unroll
                for (int ky = 0; ky < 3; ky++)
                #pragma unroll
                for (int kx = 0; kx < 3; kx++) {
                    int k = ky * 3 + kx;
                    ulonglong2 w01 = *(const ulonglong2*)(wb + k * 6);
                    ulonglong2 w23 = *(const ulonglong2*)(wb + k * 6 + 2);
                    ull w4 = wb[k * 6 + 4];
                    ull wq[5] = { w01.x, w01.y, w23.x, w23.y, w4 };
                    #pragma unroll
                    for (int q = 0; q < 5; q++) {
                        fma2(acc[q][0], rr[ky  ][kx  ], wq[q]);
                        fma2(acc[q][1], rr[ky  ][kx+1], wq[q]);
                        fma2(acc[q][2], rr[ky+1][kx  ], wq[q]);
                        fma2(acc[q][3], rr[ky+1][kx+1], wq[q]);
                    }
                }
            }
            #pragma unroll
            for (int q = 0; q < 5; q++) {
                float a0,c0,a1,c1,a2,c2,a3,c3;
                upk2(acc[q][0], a0, c0); upk2(acc[q][1], a1, c1);
                upk2(acc[q][2], a2, c2); upk2(acc[q][3], a3, c3);
                float mA = fmaxf(fmaxf(a0, a1), fmaxf(a2, a3));
                float mB = fmaxf(fmaxf(c0, c1), fmaxf(c2, c3));
                int cA = 10 * half + 2 * q;
                int jA = cA * 49 + pos, jB = jA + 49;
                if (mA >= 1.0f) atomicOr(&zT[(jA & 31) * S + s], 1u << (jA >> 5));
                if (mB >= 1.0f) atomicOr(&zT[(jB & 31) * S + s], 1u << (jB >> 5));
            }
        } else {
            // ---- half item: pool row 'sub' only (2 conv positions) ----
            unsigned m[3][4];
            int base = (2 * py + sub) * 16 + 2 * px;
            #pragma unroll
            for (int dy = 0; dy < 3; dy++) {
                const unsigned* pp = &sm->p1m[s][base + dy * 16];
                uint2 a  = *(const uint2*)&pp[0];
                uint2 bq = *(const uint2*)&pp[2];
                m[dy][0] = a.x; m[dy][1] = a.y; m[dy][2] = bq.x; m[dy][3] = bq.y;
            }
            ull acc[5][2];
            #pragma unroll
            for (int q = 0; q < 5; q++) { acc[q][0] = 0ULL; acc[q][1] = 0ULL; }

            #pragma unroll 1
            for (int ci = 0; ci < 10; ci++) {
                ull rr[3][4];
                #pragma unroll
                for (int dy = 0; dy < 3; dy++)
                #pragma unroll
                for (int dx = 0; dx < 4; dx++)
                    rr[dy][dx] = bit2f2(m[dy][dx], ci);
                const ull* wb = &sm->w2p[(half * 10 + ci) * 54];
                #pragma unroll
                for (int ky = 0; ky < 3; ky++)
                #pragma unroll
                for (int kx = 0; kx < 3; kx++) {
                    int k = ky * 3 + kx;
                    ulonglong2 w01 = *(const ulonglong2*)(wb + k * 6);
                    ulonglong2 w23 = *(const ulonglong2*)(wb + k * 6 + 2);
                    ull w4 = wb[k * 6 + 4];
                    ull wq[5] = { w01.x, w01.y, w23.x, w23.y, w4 };
                    #pragma unroll
                    for (int q = 0; q < 5; q++) {
                        fma2(acc[q][0], rr[ky][kx  ], wq[q]);
                        fma2(acc[q][1], rr[ky][kx+1], wq[q]);
                    }
                }
            }
            #pragma unroll
            for (int q = 0; q < 5; q++) {
                float a0,c0,a1,c1;
                upk2(acc[q][0], a0, c0); upk2(acc[q][1], a1, c1);
                float mA = fmaxf(a0, a1);
                float mB = fmaxf(c0, c1);
                int cA = 10 * half + 2 * q;
                int jA = cA * 49 + pos, jB = jA + 49;
                if (mA >= 1.0f) atomicOr(&zT[(jA & 31) * S + s], 1u << (jA >> 5));
                if (mB >= 1.0f) atomicOr(&zT[(jB & 31) * S + s], 1u << (jB >> 5));
            }
        }
    }
    __syncthreads();

    // ---- phase 3: fc1 — k-outer, packed sample-pair masks, 11 warps:
    //      rows i = warp + g*55 + r*11 (ghost rows i>=100 clamped+store-guarded),
    //      two sample-passes (pairs 0-3 then 4-6) to bound registers ----
    {
        unsigned zb[S];
        #pragma unroll
        for (int s = 0; s < S; s++) zb[s] = zT[lane * S + s];

        #pragma unroll 1
        for (int g = 0; g < 2; g++) {
            const int ibase = warp + g * 55;              // <= 65, always valid row
            const float* wr0 = Wf1 + (size_t)ibase * 980;
            // per-row element offsets, clamped for ghost rows (i>=100 -> row 99)
            int roff[5];
            #pragma unroll
            for (int r = 0; r < 5; r++) {
                int ri = ibase + r * 11;
                roff[r] = ((ri < 100) ? r * 11 : (99 - ibase)) * 980;
            }

            // ---- pass 0: samples 0..7 (pairs 0..3) ----
            {
                ull acc[5][4];
                #pragma unroll
                for (int r = 0; r < 5; r++)
                    #pragma unroll
                    for (int p = 0; p < 4; p++) acc[r][p] = 0ULL;

                #pragma unroll 4
                for (int k = 0; k < 31; k++) {
                    ull pm[4];
                    #pragma unroll
                    for (int p = 0; p < 4; p++) {
                        unsigned lo = ((zb[2*p]   >> k) & 1u) * 0x3f800000u;
                        unsigned hi = ((zb[2*p+1] >> k) & 1u) * 0x3f800000u;
                        asm("mov.b64 %0,{%1,%2};" : "=l"(pm[p]) : "r"(lo), "r"(hi));
                    }
                    int joff = (k < 30) ? (k * 32 + lane) : (960 + lane);
                    bool valid = (k < 30) || (lane < 20);
                    #pragma unroll
                    for (int r = 0; r < 5; r++) {
                        float w = valid ? wr0[roff[r] + joff] : 0.f;
                        ull wp = pk2(w, w);
                        fma2(acc[r][0], pm[0], wp);
                        fma2(acc[r][1], pm[1], wp);
                        fma2(acc[r][2], pm[2], wp);
                        fma2(acc[r][3], pm[3], wp);
                    }
                }
                #pragma unroll
                for (int r = 0; r < 5; r++) {
                    float f[8];
                    upk2(acc[r][0], f[0], f[1]); upk2(acc[r][1], f[2], f[3]);
                    upk2(acc[r][2], f[4], f[5]); upk2(acc[r][3], f[6], f[7]);
                    #pragma unroll
                    for (int off = 16; off; off >>= 1) {
                        #pragma unroll
                        for (int s = 0; s < 8; s++)
                            f[s] += __shfl_down_sync(0xffffffffu, f[s], off);
                    }
                    int i = ibase + r * 11;
                    if (lane == 0 && i < 100) {
                        #pragma unroll
                        for (int s = 0; s < 8; s++) sm->hs[s][i] = f[s];
                    }
                }
            }

            // ---- pass 1: samples 8..13 (pairs 4..6) ----
            {
                ull acc[5][3];
                #pragma unroll
                for (int r = 0; r < 5; r++)
                    #pragma unroll
                    for (int p = 0; p < 3; p++) acc[r][p] = 0ULL;

                #pragma unroll 4
                for (int k = 0; k < 31; k++) {
                    ull pm[3];
                    #pragma unroll
                    for (int p = 0; p < 3; p++) {
                        unsigned lo = ((zb[8+2*p] >> k) & 1u) * 0x3f800000u;
                        unsigned hi = ((zb[9+2*p] >> k) & 1u) * 0x3f800000u;
                        asm("mov.b64 %0,{%1,%2};" : "=l"(pm[p]) : "r"(lo), "r"(hi));
                    }
                    int joff = (k < 30) ? (k * 32 + lane) : (960 + lane);
                    bool valid = (k < 30) || (lane < 20);
                    #pragma unroll
                    for (int r = 0; r < 5; r++) {
                        float w = valid ? wr0[roff[r] + joff] : 0.f;
                        ull wp = pk2(w, w);
                        fma2(acc[r][0], pm[0], wp);
                        fma2(acc[r][1], pm[1], wp);
                        fma2(acc[r][2], pm[2], wp);
                    }
                }
                #pragma unroll
                for (int r = 0; r < 5; r++) {
                    float f[6];
                    upk2(acc[r][0], f[0], f[1]); upk2(acc[r][1], f[2], f[3]);
                    upk2(acc[r][2], f[4], f[5]);
                    #pragma unroll
                    for (int off = 16; off; off >>= 1) {
                        #pragma unroll
                        for (int s = 0; s < 6; s++)
                            f[s] += __shfl_down_sync(0xffffffffu, f[s], off);
                    }
                    int i = ibase + r * 11;
                    if (lane == 0 && i < 100) {
                        #pragma unroll
                        for (int s = 0; s < 6; s++) sm->hs[8 + s][i] = f[s];
                    }
                }
            }
        }
    }
    __syncthreads();

    // ---- stage A: per-neuron LIF-1 sim -> 32-bit spike train word ----
    for (int idx = t; idx < S * 100; idx += NT) {
        int s = idx / 100, i = idx - s * 100;
        float h = sm->hs[s][i], v = 0.f;
        unsigned word = 0u;
        #pragma unroll
        for (int st = 0; st < NSTEPS; st++) {
            v = v + (h - v) * 0.5f;
            if (v >= 1.0f) { word |= (1u << st); v = 0.f; }
        }
        spkw[s * 104 + i] = word;
    }
    __syncthreads();

    // ---- stage B: Y[s][t][o] = sum_i spike * Wf2  (thread = (s, t=lane)) ----
    for (int s = warp; s < S; s += 11) {
        ull y0 = 0, y1 = 0, y2 = 0, y3 = 0, y4 = 0;
        #pragma unroll 4
        for (int i = 0; i < 100; i++) {
            unsigned wbits = spkw[s * 104 + i];
            float fsp = (float)((wbits >> lane) & 1u);
            ull fp = pk2(fsp, fsp);
            const ull* wpr = sm->wf2p[i];
            ulonglong2 wA = *(const ulonglong2*)wpr;
            ulonglong2 wB = *(const ulonglong2*)(wpr + 2);
            ull w4 = wpr[4];
            fma2(y0, fp, wA.x); fma2(y1, fp, wA.y);
            fma2(y2, fp, wB.x); fma2(y3, fp, wB.y);
            fma2(y4, fp, w4);
        }
        float yo[10];
        upk2(y0, yo[0], yo[1]); upk2(y1, yo[2], yo[3]);
        upk2(y2, yo[4], yo[5]); upk2(y3, yo[6], yo[7]);
        upk2(y4, yo[8], yo[9]);
        #pragma unroll
        for (int o = 0; o < 10; o++) Y[(s * 10 + o) * 33 + lane] = yo[o];
    }
    __syncthreads();

    // ---- stage C: LIF-2 scan over t, then softmax ----
    if (t < S * 10) {
        int s = t / 10, o = t - (t / 10) * 10;
        float v2 = 0.f, cnt = 0.f;
        const float* yr = &Y[(s * 10 + o) * 33];
        #pragma unroll
        for (int st = 0; st < NSTEPS; st++) {
            float yv = yr[st];
            v2 = v2 + (yv - v2) * 0.5f;
            if (v2 >= 1.0f) { cnt += 1.0f; v2 = 0.f; }
        }
        sm->cnts[s][o] = cnt * (1.0f / 32.0f);
    }
    __syncthreads();

    if (t < S * 10) {
        int s = t / 10, o = t - (t / 10) * 10;
        if (b0 + s < B) {
            float mx = sm->cnts[s][0];
            #pragma unroll
            for (int i = 1; i < 10; i++) mx = fmaxf(mx, sm->cnts[s][i]);
            float ssum = 0.f, mine = 0.f;
            #pragma unroll
            for (int i = 0; i < 10; i++) {
                float e = expf(sm->cnts[s][i] - mx);
                ssum += e;
                if (i == o) mine = e;
            }
            out[(size_t)(b0 + s) * 10 + o] = mine / ssum;
        }
    }
}

extern "C" void kernel_launch(void* const* d_in, const int* in_sizes, int n_in,
                              void* d_out, int out_size) {
    const float* x   = (const float*)d_in[0];
    const float* Wc1 = (const float*)d_in[1];
    const float* Wc2 = (const float*)d_in[2];
    const float* Wf1 = (const float*)d_in[3];
    const float* Wf2 = (const float*)d_in[4];
    float* out = (float*)d_out;
    int B = in_sizes[0] / 784;
    int grid = (B + S - 1) / S;
    size_t smem = sizeof(Smem);
    cudaFuncSetAttribute(snn_fused_kernel,
                         cudaFuncAttributeMaxDynamicSharedMemorySize, (int)smem);
    snn_fused_kernel<<<grid, NT, smem>>>(x, Wc1, Wc2, Wf1, Wf2, out, B);
}

// round 16
// speedup vs baseline: 1.0743x; 1.0743x over previous
#include <cuda_runtime.h>

#define S 14
#define NT 320
#define NSTEPS 32

typedef unsigned long long ull;

__device__ __forceinline__ ull pk2(float lo, float hi) {
    ull r; asm("mov.b64 %0,{%1,%2};" : "=l"(r) : "f"(lo), "f"(hi)); return r;
}
__device__ __forceinline__ void upk2(ull v, float& lo, float& hi) {
    asm("mov.b64 {%0,%1},%2;" : "=f"(lo), "=f"(hi) : "l"(v));
}
__device__ __forceinline__ void fma2(ull& d, ull a, ull b) {
    asm("fma.rn.f32x2 %0,%1,%2,%3;" : "=l"(d) : "l"(a), "l"(b), "l"(d));
}
// replicate one-bit -> {1.0f,1.0f} or {0,0} packed, no I2F
__device__ __forceinline__ ull bit2f2(unsigned m, int ci) {
    unsigned fb = ((m >> ci) & 1u) * 0x3f800000u;
    ull r; asm("mov.b64 %0,{%1,%1};" : "=l"(r) : "r"(fb)); return r;
}

// phase-2 scheduling: 14*98 = 1372 full items -> 1144 full + 456 halves = 1600 = 5*NT
#define P2_FULL 1144
#define P2_SCHED 1600

struct __align__(16) Smem {
    char uA[50432];              // xp[S][900] (ph0-1) | spkw[S][104] @0 | Y[S*10][33] @8192
    unsigned p1m[S][256];        // 16x16 padded, 10-bit channel mask
    ull w1p[45];                 // conv1 weights, channel pairs
    __align__(16) ull w2p[1080]; // conv2 weights [half][ci][k][6] (pad q=5 -> 0)
    __align__(16) ull wf2p[100][6];  // fc2 weights, o-pairs (pad [5]=0)
    unsigned zTm[32 * S];        // [lane][s]: bit k = z[k*32+lane] of sample s
    float hs[S][100];
    float cnts[S][10];
};

__global__ __launch_bounds__(NT, 2) void snn_fused_kernel(
    const float* __restrict__ x,    // [B,1,28,28]
    const float* __restrict__ Wc1,  // [10,1,3,3]
    const float* __restrict__ Wc2,  // [20,10,3,3]
    const float* __restrict__ Wf1,  // [100,980]
    const float* __restrict__ Wf2,  // [10,100]
    float* __restrict__ out,        // [B,10]
    int B)
{
    extern __shared__ __align__(16) char smem_raw[];
    Smem* sm = (Smem*)smem_raw;

    float*    xp   = (float*)sm->uA;              // [S][900]   (ph0-1)
    unsigned* spkw = (unsigned*)sm->uA;           // [S][104]   (stage A+)
    float*    Y    = (float*)(sm->uA + 8192);     // [S*10][33] (stage B+)
    unsigned* zT   = sm->zTm;

    const int t  = threadIdx.x;
    const int b0 = blockIdx.x * S;
    const int warp = t >> 5, lane = t & 31;

    // ---- init: HALO-ONLY zeroing (interior fully overwritten later) + weights.
    //      Halo-zero writes are disjoint from interior staging writes, so init
    //      and staging share ONE barrier interval.
    // xp halo: 116 cells/sample (rows 0,29 full; cols 0,29 rows 1-28)
    for (int i = t; i < S * 116; i += NT) {
        int s = i / 116, j = i - s * 116;
        int y, c;
        if (j < 30)      { y = 0;        c = j; }
        else if (j < 60) { y = 29;       c = j - 30; }
        else if (j < 88) { y = 1 + (j - 60);  c = 0; }
        else             { y = 1 + (j - 88);  c = 29; }
        xp[s * 900 + y * 30 + c] = 0.f;
    }
    // p1m halo: 60 cells/sample (rows 0,15 full; cols 0,15 rows 1-14)
    for (int i = t; i < S * 60; i += NT) {
        int s = i / 60, j = i - s * 60;
        int y, c;
        if (j < 16)      { y = 0;        c = j; }
        else if (j < 32) { y = 15;       c = j - 16; }
        else if (j < 46) { y = 1 + (j - 32);  c = 0; }
        else             { y = 1 + (j - 46);  c = 15; }
        sm->p1m[s][y * 16 + c] = 0u;
    }
    for (int i = t; i < 32 * S; i += NT) zT[i] = 0u;
    for (int i = t; i < 45; i += NT) {
        int cp = i / 9, k = i - cp * 9;
        sm->w1p[i] = pk2(Wc1[(2 * cp) * 9 + k], Wc1[(2 * cp + 1) * 9 + k]);
    }
    for (int i = t; i < 1080; i += NT) {
        int q6 = i % 6, k = (i / 6) % 9, ci = (i / 54) % 10, half = i / 540;
        if (q6 < 5) {
            int cA = half * 10 + 2 * q6;
            sm->w2p[i] = pk2(Wc2[cA * 90 + ci * 9 + k], Wc2[(cA + 1) * 90 + ci * 9 + k]);
        } else sm->w2p[i] = 0ULL;
    }
    for (int i = t; i < 600; i += NT) {
        int ii = i / 6, q = i - (i / 6) * 6;
        sm->wf2p[ii][q] = (q < 5) ? pk2(Wf2[(2 * q) * 100 + ii], Wf2[(2 * q + 1) * 100 + ii]) : 0ULL;
    }

    // ---- stage inputs, same barrier interval (interior cells only) ----
    for (int i = t; i < S * 196; i += NT) {
        int s = i / 196, j4 = i - s * 196;
        if (b0 + s < B) {
            int y = j4 / 7, c4 = (j4 - y * 7) * 4;
            float4 v = ((const float4*)(x + (size_t)(b0 + s) * 784))[j4];
            float* dst = &xp[s * 900 + (y + 1) * 30 + (c4 + 1)];
            dst[0] = v.x; dst[1] = v.y; dst[2] = v.z; dst[3] = v.w;
        }
    }
    __syncthreads();

    // ---- phase 1: conv1(1->10)+spike+pool, f32x2 over 5 channel pairs ----
    for (int idx = t; idx < S * 196; idx += NT) {
        int s   = idx / 196;
        int pos = idx - s * 196;
        int py = pos / 14, px = pos - py * 14;

        ull rr[4][4];
        {
            int base = s * 900 + (2 * py) * 30 + 2 * px;   // even -> 8B aligned
            #pragma unroll
            for (int dy = 0; dy < 4; dy++) {
                float2 a  = *(const float2*)&xp[base + dy * 30];
                float2 bq = *(const float2*)&xp[base + dy * 30 + 2];
                rr[dy][0] = pk2(a.x, a.x);  rr[dy][1] = pk2(a.y, a.y);
                rr[dy][2] = pk2(bq.x, bq.x); rr[dy][3] = pk2(bq.y, bq.y);
            }
        }
        ull acc[5][4];
        #pragma unroll
        for (int q = 0; q < 5; q++)
            #pragma unroll
            for (int p = 0; p < 4; p++) acc[q][p] = 0ULL;

        #pragma unroll
        for (int ky = 0; ky < 3; ky++)
        #pragma unroll
        for (int kx = 0; kx < 3; kx++) {
            int k = ky * 3 + kx;
            #pragma unroll
            for (int q = 0; q < 5; q++) {
                ull wp = sm->w1p[q * 9 + k];
                fma2(acc[q][0], rr[ky  ][kx  ], wp);
                fma2(acc[q][1], rr[ky  ][kx+1], wp);
                fma2(acc[q][2], rr[ky+1][kx  ], wp);
                fma2(acc[q][3], rr[ky+1][kx+1], wp);
            }
        }
        unsigned mask = 0u;
        #pragma unroll
        for (int q = 0; q < 5; q++) {
            float a0,b0v,a1,b1v,a2,b2v,a3,b3v;
            upk2(acc[q][0], a0, b0v); upk2(acc[q][1], a1, b1v);
            upk2(acc[q][2], a2, b2v); upk2(acc[q][3], a3, b3v);
            float mA = fmaxf(fmaxf(a0, a1), fmaxf(a2, a3));
            float mB = fmaxf(fmaxf(b0v, b1v), fmaxf(b2v, b3v));
            if (mA >= 1.0f) mask |= (1u << (2 * q));
            if (mB >= 1.0f) mask |= (1u << (2 * q + 1));
        }
        sm->p1m[s][(py + 1) * 16 + (px + 1)] = mask;
    }
    __syncthreads();

    // ---- phase 2: conv2(10->20)+spike+pool -> z bits into zT ----
    // 1600 = 5*NT scheduled: idx<P2_FULL full (2x2 window); rest half-items
    // (one pool row each; halves OR into the same z bit — max == OR of fires)
    for (int idx = t; idx < P2_SCHED; idx += NT) {
        int orig, sub;
        if (idx < P2_FULL) { orig = idx; sub = -1; }
        else { int j = idx - P2_FULL; orig = P2_FULL + (j >> 1); sub = j & 1; }
        int s    = orig / 98;
        int rem  = orig - s * 98;
        int half = rem / 49;
        int pos  = rem - half * 49;
        int py = pos / 7, px = pos - py * 7;

        if (sub < 0) {
            // ---- full item: 4 conv positions ----
            unsigned m[4][4];
            int base = (2 * py) * 16 + 2 * px;
            #pragma unroll
            for (int dy = 0; dy < 4; dy++) {
                const unsigned* pp = &sm->p1m[s][base + dy * 16];
                uint2 a  = *(const uint2*)&pp[0];
                uint2 bq = *(const uint2*)&pp[2];
                m[dy][0] = a.x; m[dy][1] = a.y; m[dy][2] = bq.x; m[dy][3] = bq.y;
            }
            ull acc[5][4];
            #pragma unroll
            for (int q = 0; q < 5; q++)
                #pragma unroll
                for (int p = 0; p < 4; p++) acc[q][p] = 0ULL;

            #pragma unroll 1
            for (int ci = 0; ci < 10; ci++) {
                ull rr[4][4];
                #pragma unroll
                for (int dy = 0; dy < 4; dy++)
                #pragma unroll
                for (int dx = 0; dx < 4; dx++)
                    rr[dy][dx] = bit2f2(m[dy][dx], ci);
                const ull* wb = &sm->w2p[(half * 10 + ci) * 54];
                #pragma unroll
                for (int ky = 0; ky < 3; ky++)
                #pragma unroll
                for (int kx = 0; kx < 3; kx++) {
                    int k = ky * 3 + kx;
                    ulonglong2 w01 = *(const ulonglong2*)(wb + k * 6);
                    ulonglong2 w23 = *(const ulonglong2*)(wb + k * 6 + 2);
                    ull w4 = wb[k * 6 + 4];
                    ull wq[5] = { w01.x, w01.y, w23.x, w23.y, w4 };
                    #pragma unroll
                    for (int q = 0; q < 5; q++) {
                        fma2(acc[q][0], rr[ky  ][kx  ], wq[q]);
                        fma2(acc[q][1], rr[ky  ][kx+1], wq[q]);
                        fma2(acc[q][2], rr[ky+1][kx  ], wq[q]);
                        fma2(acc[q][3], rr[ky+1][kx+1], wq[q]);
                    }
                }
            }
            #pragma unroll
            for (int q = 0; q < 5; q++) {
                float a0,c0,a1,c1,a2,c2,a3,c3;
                upk2(acc[q][0], a0, c0); upk2(acc[q][1], a1, c1);
                upk2(acc[q][2], a2, c2); upk2(acc[q][3], a3, c3);
                float mA = fmaxf(fmaxf(a0, a1), fmaxf(a2, a3));
                float mB = fmaxf(fmaxf(c0, c1), fmaxf(c2, c3));
                int cA = 10 * half + 2 * q;
                int jA = cA * 49 + pos, jB = jA + 49;
                if (mA >= 1.0f) atomicOr(&zT[(jA & 31) * S + s], 1u << (jA >> 5));
                if (mB >= 1.0f) atomicOr(&zT[(jB & 31) * S + s], 1u << (jB >> 5));
            }
        } else {
            // ---- half item: pool row 'sub' only (2 conv positions) ----
            unsigned m[3][4];
            int base = (2 * py + sub) * 16 + 2 * px;
            #pragma unroll
            for (int dy = 0; dy < 3; dy++) {
                const unsigned* pp = &sm->p1m[s][base + dy * 16];
                uint2 a  = *(const uint2*)&pp[0];
                uint2 bq = *(const uint2*)&pp[2];
                m[dy][0] = a.x; m[dy][1] = a.y; m[dy][2] = bq.x; m[dy][3] = bq.y;
            }
            ull acc[5][2];
            #pragma unroll
            for (int q = 0; q < 5; q++) { acc[q][0] = 0ULL; acc[q][1] = 0ULL; }

            #pragma unroll 1
            for (int ci = 0; ci < 10; ci++) {
                ull rr[3][4];
                #pragma unroll
                for (int dy = 0; dy < 3; dy++)
                #pragma unroll
                for (int dx = 0; dx < 4; dx++)
                    rr[dy][dx] = bit2f2(m[dy][dx], ci);
                const ull* wb = &sm->w2p[(half * 10 + ci) * 54];
                #pragma unroll
                for (int ky = 0; ky < 3; ky++)
                #pragma unroll
                for (int kx = 0; kx < 3; kx++) {
                    int k = ky * 3 + kx;
                    ulonglong2 w01 = *(const ulonglong2*)(wb + k * 6);
                    ulonglong2 w23 = *(const ulonglong2*)(wb + k * 6 + 2);
                    ull w4 = wb[k * 6 + 4];
                    ull wq[5] = { w01.x, w01.y, w23.x, w23.y, w4 };
                    #pragma unroll
                    for (int q = 0; q < 5; q++) {
                        fma2(acc[q][0], rr[ky][kx  ], wq[q]);
                        fma2(acc[q][1], rr[ky][kx+1], wq[q]);
                    }
                }
            }
            #pragma unroll
            for (int q = 0; q < 5; q++) {
                float a0,c0,a1,c1;
                upk2(acc[q][0], a0, c0); upk2(acc[q][1], a1, c1);
                float mA = fmaxf(a0, a1);
                float mB = fmaxf(c0, c1);
                int cA = 10 * half + 2 * q;
                int jA = cA * 49 + pos, jB = jA + 49;
                if (mA >= 1.0f) atomicOr(&zT[(jA & 31) * S + s], 1u << (jA >> 5));
                if (mB >= 1.0f) atomicOr(&zT[(jB & 31) * S + s], 1u << (jB >> 5));
            }
        }
    }
    __syncthreads();

    // ---- phase 3: fc1 — k-outer, packed sample-pair masks, 5-row groups,
    //      two sample-passes (pairs 0-3 then 4-6) to bound registers ----
    {
        unsigned zb[S];
        #pragma unroll
        for (int s = 0; s < S; s++) zb[s] = zT[lane * S + s];

        #pragma unroll 1
        for (int g = 0; g < 2; g++) {
            const float* wr0 = Wf1 + (size_t)(warp + g * 50) * 980;

            // ---- pass 0: samples 0..7 (pairs 0..3) ----
            {
                ull acc[5][4];
                #pragma unroll
                for (int r = 0; r < 5; r++)
                    #pragma unroll
                    for (int p = 0; p < 4; p++) acc[r][p] = 0ULL;

                #pragma unroll 4
                for (int k = 0; k < 31; k++) {
                    ull pm[4];
                    #pragma unroll
                    for (int p = 0; p < 4; p++) {
                        unsigned lo = ((zb[2*p]   >> k) & 1u) * 0x3f800000u;
                        unsigned hi = ((zb[2*p+1] >> k) & 1u) * 0x3f800000u;
                        asm("mov.b64 %0,{%1,%2};" : "=l"(pm[p]) : "r"(lo), "r"(hi));
                    }
                    int joff = (k < 30) ? (k * 32 + lane) : (960 + lane);
                    bool valid = (k < 30) || (lane < 20);
                    #pragma unroll
                    for (int r = 0; r < 5; r++) {
                        float w = valid ? wr0[r * 9800 + joff] : 0.f;
                        ull wp = pk2(w, w);
                        fma2(acc[r][0], pm[0], wp);
                        fma2(acc[r][1], pm[1], wp);
                        fma2(acc[r][2], pm[2], wp);
                        fma2(acc[r][3], pm[3], wp);
                    }
                }
                #pragma unroll
                for (int r = 0; r < 5; r++) {
                    float f[8];
                    upk2(acc[r][0], f[0], f[1]); upk2(acc[r][1], f[2], f[3]);
                    upk2(acc[r][2], f[4], f[5]); upk2(acc[r][3], f[6], f[7]);
                    #pragma unroll
                    for (int off = 16; off; off >>= 1) {
                        #pragma unroll
                        for (int s = 0; s < 8; s++)
                            f[s] += __shfl_down_sync(0xffffffffu, f[s], off);
                    }
                    if (lane == 0) {
                        int i = warp + g * 50 + r * 10;
                        #pragma unroll
                        for (int s = 0; s < 8; s++) sm->hs[s][i] = f[s];
                    }
                }
            }

            // ---- pass 1: samples 8..13 (pairs 4..6) ----
            {
                ull acc[5][3];
                #pragma unroll
                for (int r = 0; r < 5; r++)
                    #pragma unroll
                    for (int p = 0; p < 3; p++) acc[r][p] = 0ULL;

                #pragma unroll 4
                for (int k = 0; k < 31; k++) {
                    ull pm[3];
                    #pragma unroll
                    for (int p = 0; p < 3; p++) {
                        unsigned lo = ((zb[8+2*p] >> k) & 1u) * 0x3f800000u;
                        unsigned hi = ((zb[9+2*p] >> k) & 1u) * 0x3f800000u;
                        asm("mov.b64 %0,{%1,%2};" : "=l"(pm[p]) : "r"(lo), "r"(hi));
                    }
                    int joff = (k < 30) ? (k * 32 + lane) : (960 + lane);
                    bool valid = (k < 30) || (lane < 20);
                    #pragma unroll
                    for (int r = 0; r < 5; r++) {
                        float w = valid ? wr0[r * 9800 + joff] : 0.f;
                        ull wp = pk2(w, w);
                        fma2(acc[r][0], pm[0], wp);
                        fma2(acc[r][1], pm[1], wp);
                        fma2(acc[r][2], pm[2], wp);
                    }
                }
                #pragma unroll
                for (int r = 0; r < 5; r++) {
                    float f[6];
                    upk2(acc[r][0], f[0], f[1]); upk2(acc[r][1], f[2], f[3]);
                    upk2(acc[r][2], f[4], f[5]);
                    #pragma unroll
                    for (int off = 16; off; off >>= 1) {
                        #pragma unroll
                        for (int s = 0; s < 6; s++)
                            f[s] += __shfl_down_sync(0xffffffffu, f[s], off);
                    }
                    if (lane == 0) {
                        int i = warp + g * 50 + r * 10;
                        #pragma unroll
                        for (int s = 0; s < 6; s++) sm->hs[8 + s][i] = f[s];
                    }
                }
            }
        }
    }
    __syncthreads();

    // ---- stage A: per-neuron LIF-1 sim -> 32-bit spike train word ----
    for (int idx = t; idx < S * 100; idx += NT) {
        int s = idx / 100, i = idx - s * 100;
        float h = sm->hs[s][i], v = 0.f;
        unsigned word = 0u;
        #pragma unroll
        for (int st = 0; st < NSTEPS; st++) {
            v = v + (h - v) * 0.5f;
            if (v >= 1.0f) { word |= (1u << st); v = 0.f; }
        }
        spkw[s * 104 + i] = word;
    }
    __syncthreads();

    // ---- stage B: Y[s][t][o] = sum_i spike * Wf2  (thread = (s, t=lane)) ----
    for (int s = warp; s < S; s += 10) {
        ull y0 = 0, y1 = 0, y2 = 0, y3 = 0, y4 = 0;
        #pragma unroll 4
        for (int i = 0; i < 100; i++) {
            unsigned wbits = spkw[s * 104 + i];
            float fsp = (float)((wbits >> lane) & 1u);
            ull fp = pk2(fsp, fsp);
            const ull* wpr = sm->wf2p[i];
            ulonglong2 wA = *(const ulonglong2*)wpr;
            ulonglong2 wB = *(const ulonglong2*)(wpr + 2);
            ull w4 = wpr[4];
            fma2(y0, fp, wA.x); fma2(y1, fp, wA.y);
            fma2(y2, fp, wB.x); fma2(y3, fp, wB.y);
            fma2(y4, fp, w4);
        }
        float yo[10];
        upk2(y0, yo[0], yo[1]); upk2(y1, yo[2], yo[3]);
        upk2(y2, yo[4], yo[5]); upk2(y3, yo[6], yo[7]);
        upk2(y4, yo[8], yo[9]);
        #pragma unroll
        for (int o = 0; o < 10; o++) Y[(s * 10 + o) * 33 + lane] = yo[o];
    }
    __syncthreads();

    // ---- stage C: LIF-2 scan over t, then softmax ----
    if (t < S * 10) {
        int s = t / 10, o = t - (t / 10) * 10;
        float v2 = 0.f, cnt = 0.f;
        const float* yr = &Y[(s * 10 + o) * 33];
        #pragma unroll
        for (int st = 0; st < NSTEPS; st++) {
            float yv = yr[st];
            v2 = v2 + (yv - v2) * 0.5f;
            if (v2 >= 1.0f) { cnt += 1.0f; v2 = 0.f; }
        }
        sm->cnts[s][o] = cnt * (1.0f / 32.0f);
    }
    __syncthreads();

    if (t < S * 10) {
        int s = t / 10, o = t - (t / 10) * 10;
        if (b0 + s < B) {
            float mx = sm->cnts[s][0];
            #pragma unroll
            for (int i = 1; i < 10; i++) mx = fmaxf(mx, sm->cnts[s][i]);
            float ssum = 0.f, mine = 0.f;
            #pragma unroll
            for (int i = 0; i < 10; i++) {
                float e = expf(sm->cnts[s][i] - mx);
                ssum += e;
                if (i == o) mine = e;
            }
            out[(size_t)(b0 + s) * 10 + o] = mine / ssum;
        }
    }
}

extern "C" void kernel_launch(void* const* d_in, const int* in_sizes, int n_in,
                              void* d_out, int out_size) {
    const float* x   = (const float*)d_in[0];
    const float* Wc1 = (const float*)d_in[1];
    const float* Wc2 = (const float*)d_in[2];
    const float* Wf1 = (const float*)d_in[3];
    const float* Wf2 = (const float*)d_in[4];
    float* out = (float*)d_out;
    int B = in_sizes[0] / 784;
    int grid = (B + S - 1) / S;
    size_t smem = sizeof(Smem);
    cudaFuncSetAttribute(snn_fused_kernel,
                         cudaFuncAttributeMaxDynamicSharedMemorySize, (int)smem);
    snn_fused_kernel<<<grid, NT, smem>>>(x, Wc1, Wc2, Wf1, Wf2, out, B);
}

// round 17
// speedup vs baseline: 1.1440x; 1.0649x over previous
#include <cuda_runtime.h>

#define S 14
#define NT 320
#define NSTEPS 32

typedef unsigned long long ull;

__device__ __forceinline__ ull pk2(float lo, float hi) {
    ull r; asm("mov.b64 %0,{%1,%2};" : "=l"(r) : "f"(lo), "f"(hi)); return r;
}
__device__ __forceinline__ void upk2(ull v, float& lo, float& hi) {
    asm("mov.b64 {%0,%1},%2;" : "=f"(lo), "=f"(hi) : "l"(v));
}
__device__ __forceinline__ void fma2(ull& d, ull a, ull b) {
    asm("fma.rn.f32x2 %0,%1,%2,%3;" : "=l"(d) : "l"(a), "l"(b), "l"(d));
}
// replicate one-bit -> {1.0f,1.0f} or {0,0} packed; NEG+AND keeps it off the fma pipe
__device__ __forceinline__ ull bit2f2(unsigned m, int ci) {
    unsigned fb = (0u - ((m >> ci) & 1u)) & 0x3f800000u;
    ull r; asm("mov.b64 %0,{%1,%1};" : "=l"(r) : "r"(fb)); return r;
}
// one-bit -> 1.0f/0.0f bits (alu-pipe form)
__device__ __forceinline__ unsigned bitf(unsigned z, int k) {
    return (0u - ((z >> k) & 1u)) & 0x3f800000u;
}

// phase-2 scheduling: 14*98 = 1372 full items -> 1144 full + 456 halves = 1600 = 5*NT
#define P2_FULL 1144
#define P2_SCHED 1600

struct __align__(16) Smem {
    char uA[50432];              // xp[S][900] (ph0-1) | spkw[S][104] @0 | Y[S*10][33] @8192
    unsigned p1m[S][256];        // 16x16 padded, 10-bit channel mask
    ull w1p[45];                 // conv1 weights, channel pairs
    __align__(16) ull w2p[1080]; // conv2 weights [half][ci][k][6] (pad q=5 -> 0)
    __align__(16) ull wf2p[100][6];  // fc2 weights, o-pairs (pad [5]=0)
    unsigned zTm[32 * S];        // [lane][s]: bit k = z[k*32+lane] of sample s
    float hs[S][100];
    float cnts[S][10];
};

__global__ __launch_bounds__(NT, 2) void snn_fused_kernel(
    const float* __restrict__ x,    // [B,1,28,28]
    const float* __restrict__ Wc1,  // [10,1,3,3]
    const float* __restrict__ Wc2,  // [20,10,3,3]
    const float* __restrict__ Wf1,  // [100,980]
    const float* __restrict__ Wf2,  // [10,100]
    float* __restrict__ out,        // [B,10]
    int B)
{
    extern __shared__ __align__(16) char smem_raw[];
    Smem* sm = (Smem*)smem_raw;

    float*    xp   = (float*)sm->uA;              // [S][900]   (ph0-1)
    unsigned* spkw = (unsigned*)sm->uA;           // [S][104]   (stage A+)
    float*    Y    = (float*)(sm->uA + 8192);     // [S*10][33] (stage B+)
    unsigned* zT   = sm->zTm;

    const int t  = threadIdx.x;
    const int b0 = blockIdx.x * S;
    const int warp = t >> 5, lane = t & 31;

    // ---- init: HALO-ONLY zeroing (interior fully overwritten later) + weights.
    for (int i = t; i < S * 116; i += NT) {
        int s = i / 116, j = i - s * 116;
        int y, c;
        if (j < 30)      { y = 0;        c = j; }
        else if (j < 60) { y = 29;       c = j - 30; }
        else if (j < 88) { y = 1 + (j - 60);  c = 0; }
        else             { y = 1 + (j - 88);  c = 29; }
        xp[s * 900 + y * 30 + c] = 0.f;
    }
    for (int i = t; i < S * 60; i += NT) {
        int s = i / 60, j = i - s * 60;
        int y, c;
        if (j < 16)      { y = 0;        c = j; }
        else if (j < 32) { y = 15;       c = j - 16; }
        else if (j < 46) { y = 1 + (j - 32);  c = 0; }
        else             { y = 1 + (j - 46);  c = 15; }
        sm->p1m[s][y * 16 + c] = 0u;
    }
    for (int i = t; i < 32 * S; i += NT) zT[i] = 0u;
    for (int i = t; i < 45; i += NT) {
        int cp = i / 9, k = i - cp * 9;
        sm->w1p[i] = pk2(Wc1[(2 * cp) * 9 + k], Wc1[(2 * cp + 1) * 9 + k]);
    }
    for (int i = t; i < 1080; i += NT) {
        int q6 = i % 6, k = (i / 6) % 9, ci = (i / 54) % 10, half = i / 540;
        if (q6 < 5) {
            int cA = half * 10 + 2 * q6;
            sm->w2p[i] = pk2(Wc2[cA * 90 + ci * 9 + k], Wc2[(cA + 1) * 90 + ci * 9 + k]);
        } else sm->w2p[i] = 0ULL;
    }
    for (int i = t; i < 600; i += NT) {
        int ii = i / 6, q = i - (i / 6) * 6;
        sm->wf2p[ii][q] = (q < 5) ? pk2(Wf2[(2 * q) * 100 + ii], Wf2[(2 * q + 1) * 100 + ii]) : 0ULL;
    }

    // ---- stage inputs, same barrier interval (interior cells only) ----
    for (int i = t; i < S * 196; i += NT) {
        int s = i / 196, j4 = i - s * 196;
        if (b0 + s < B) {
            int y = j4 / 7, c4 = (j4 - y * 7) * 4;
            float4 v = ((const float4*)(x + (size_t)(b0 + s) * 784))[j4];
            float* dst = &xp[s * 900 + (y + 1) * 30 + (c4 + 1)];
            dst[0] = v.x; dst[1] = v.y; dst[2] = v.z; dst[3] = v.w;
        }
    }
    __syncthreads();

    // ---- phase 1: conv1(1->10)+spike+pool, f32x2 over 5 channel pairs ----
    for (int idx = t; idx < S * 196; idx += NT) {
        int s   = idx / 196;
        int pos = idx - s * 196;
        int py = pos / 14, px = pos - py * 14;

        ull rr[4][4];
        {
            int base = s * 900 + (2 * py) * 30 + 2 * px;   // even -> 8B aligned
            #pragma unroll
            for (int dy = 0; dy < 4; dy++) {
                float2 a  = *(const float2*)&xp[base + dy * 30];
                float2 bq = *(const float2*)&xp[base + dy * 30 + 2];
                rr[dy][0] = pk2(a.x, a.x);  rr[dy][1] = pk2(a.y, a.y);
                rr[dy][2] = pk2(bq.x, bq.x); rr[dy][3] = pk2(bq.y, bq.y);
            }
        }
        ull acc[5][4];
        #pragma unroll
        for (int q = 0; q < 5; q++)
            #pragma unroll
            for (int p = 0; p < 4; p++) acc[q][p] = 0ULL;

        #pragma unroll
        for (int ky = 0; ky < 3; ky++)
        #pragma unroll
        for (int kx = 0; kx < 3; kx++) {
            int k = ky * 3 + kx;
            #pragma unroll
            for (int q = 0; q < 5; q++) {
                ull wp = sm->w1p[q * 9 + k];
                fma2(acc[q][0], rr[ky  ][kx  ], wp);
                fma2(acc[q][1], rr[ky  ][kx+1], wp);
                fma2(acc[q][2], rr[ky+1][kx  ], wp);
                fma2(acc[q][3], rr[ky+1][kx+1], wp);
            }
        }
        unsigned mask = 0u;
        #pragma unroll
        for (int q = 0; q < 5; q++) {
            float a0,b0v,a1,b1v,a2,b2v,a3,b3v;
            upk2(acc[q][0], a0, b0v); upk2(acc[q][1], a1, b1v);
            upk2(acc[q][2], a2, b2v); upk2(acc[q][3], a3, b3v);
            float mA = fmaxf(fmaxf(a0, a1), fmaxf(a2, a3));
            float mB = fmaxf(fmaxf(b0v, b1v), fmaxf(b2v, b3v));
            if (mA >= 1.0f) mask |= (1u << (2 * q));
            if (mB >= 1.0f) mask |= (1u << (2 * q + 1));
        }
        sm->p1m[s][(py + 1) * 16 + (px + 1)] = mask;
    }
    __syncthreads();

    // ---- phase 2: conv2(10->20)+spike+pool -> z bits into zT ----
    for (int idx = t; idx < P2_SCHED; idx += NT) {
        int orig, sub;
        if (idx < P2_FULL) { orig = idx; sub = -1; }
        else { int j = idx - P2_FULL; orig = P2_FULL + (j >> 1); sub = j & 1; }
        int s    = orig / 98;
        int rem  = orig - s * 98;
        int half = rem / 49;
        int pos  = rem - half * 49;
        int py = pos / 7, px = pos - py * 7;

        if (sub < 0) {
            // ---- full item: 4 conv positions ----
            unsigned m[4][4];
            int base = (2 * py) * 16 + 2 * px;
            #pragma unroll
            for (int dy = 0; dy < 4; dy++) {
                const unsigned* pp = &sm->p1m[s][base + dy * 16];
                uint2 a  = *(const uint2*)&pp[0];
                uint2 bq = *(const uint2*)&pp[2];
                m[dy][0] = a.x; m[dy][1] = a.y; m[dy][2] = bq.x; m[dy][3] = bq.y;
            }
            ull acc[5][4];
            #pragma unroll
            for (int q = 0; q < 5; q++)
                #pragma unroll
                for (int p = 0; p < 4; p++) acc[q][p] = 0ULL;

            #pragma unroll 1
            for (int ci = 0; ci < 10; ci++) {
                ull rr[4][4];
                #pragma unroll
                for (int dy = 0; dy < 4; dy++)
                #pragma unroll
                for (int dx = 0; dx < 4; dx++)
                    rr[dy][dx] = bit2f2(m[dy][dx], ci);
                const ull* wb = &sm->w2p[(half * 10 + ci) * 54];
                #pragma unroll
                for (int ky = 0; ky < 3; ky++)
                #pragma unroll
                for (int kx = 0; kx < 3; kx++) {
                    int k = ky * 3 + kx;
                    ulonglong2 w01 = *(const ulonglong2*)(wb + k * 6);
                    ulonglong2 w23 = *(const ulonglong2*)(wb + k * 6 + 2);
                    ull w4 = wb[k * 6 + 4];
                    ull wq[5] = { w01.x, w01.y, w23.x, w23.y, w4 };
                    #pragma unroll
                    for (int q = 0; q < 5; q++) {
                        fma2(acc[q][0], rr[ky  ][kx  ], wq[q]);
                        fma2(acc[q][1], rr[ky  ][kx+1], wq[q]);
                        fma2(acc[q][2], rr[ky+1][kx  ], wq[q]);
                        fma2(acc[q][3], rr[ky+1][kx+1], wq[q]);
                    }
                }
            }
            #pragma unroll
            for (int q = 0; q < 5; q++) {
                float a0,c0,a1,c1,a2,c2,a3,c3;
                upk2(acc[q][0], a0, c0); upk2(acc[q][1], a1, c1);
                upk2(acc[q][2], a2, c2); upk2(acc[q][3], a3, c3);
                float mA = fmaxf(fmaxf(a0, a1), fmaxf(a2, a3));
                float mB = fmaxf(fmaxf(c0, c1), fmaxf(c2, c3));
                int cA = 10 * half + 2 * q;
                int jA = cA * 49 + pos, jB = jA + 49;
                if (mA >= 1.0f) atomicOr(&zT[(jA & 31) * S + s], 1u << (jA >> 5));
                if (mB >= 1.0f) atomicOr(&zT[(jB & 31) * S + s], 1u << (jB >> 5));
            }
        } else {
            // ---- half item: pool row 'sub' only (2 conv positions) ----
            unsigned m[3][4];
            int base = (2 * py + sub) * 16 + 2 * px;
            #pragma unroll
            for (int dy = 0; dy < 3; dy++) {
                const unsigned* pp = &sm->p1m[s][base + dy * 16];
                uint2 a  = *(const uint2*)&pp[0];
                uint2 bq = *(const uint2*)&pp[2];
                m[dy][0] = a.x; m[dy][1] = a.y; m[dy][2] = bq.x; m[dy][3] = bq.y;
            }
            ull acc[5][2];
            #pragma unroll
            for (int q = 0; q < 5; q++) { acc[q][0] = 0ULL; acc[q][1] = 0ULL; }

            #pragma unroll 1
            for (int ci = 0; ci < 10; ci++) {
                ull rr[3][4];
                #pragma unroll
                for (int dy = 0; dy < 3; dy++)
                #pragma unroll
                for (int dx = 0; dx < 4; dx++)
                    rr[dy][dx] = bit2f2(m[dy][dx], ci);
                const ull* wb = &sm->w2p[(half * 10 + ci) * 54];
                #pragma unroll
                for (int ky = 0; ky < 3; ky++)
                #pragma unroll
                for (int kx = 0; kx < 3; kx++) {
                    int k = ky * 3 + kx;
                    ulonglong2 w01 = *(const ulonglong2*)(wb + k * 6);
                    ulonglong2 w23 = *(const ulonglong2*)(wb + k * 6 + 2);
                    ull w4 = wb[k * 6 + 4];
                    ull wq[5] = { w01.x, w01.y, w23.x, w23.y, w4 };
                    #pragma unroll
                    for (int q = 0; q < 5; q++) {
                        fma2(acc[q][0], rr[ky][kx  ], wq[q]);
                        fma2(acc[q][1], rr[ky][kx+1], wq[q]);
                    }
                }
            }
            #pragma unroll
            for (int q = 0; q < 5; q++) {
                float a0,c0,a1,c1;
                upk2(acc[q][0], a0, c0); upk2(acc[q][1], a1, c1);
                float mA = fmaxf(a0, a1);
                float mB = fmaxf(c0, c1);
                int cA = 10 * half + 2 * q;
                int jA = cA * 49 + pos, jB = jA + 49;
                if (mA >= 1.0f) atomicOr(&zT[(jA & 31) * S + s], 1u << (jA >> 5));
                if (mB >= 1.0f) atomicOr(&zT[(jB & 31) * S + s], 1u << (jB >> 5));
            }
        }
    }
    __syncthreads();

    // ---- phase 3: fc1 — k-outer, packed sample-pair masks, 5-row groups,
    //      two sample-passes; k-loop split 0..29 + explicit k=30 tail ----
    {
        unsigned zb[S];
        #pragma unroll
        for (int s = 0; s < S; s++) zb[s] = zT[lane * S + s];

        #pragma unroll 1
        for (int g = 0; g < 2; g++) {
            const float* wr0 = Wf1 + (size_t)(warp + g * 50) * 980;

            // ---- pass 0: samples 0..7 (pairs 0..3) ----
            {
                ull acc[5][4];
                #pragma unroll
                for (int r = 0; r < 5; r++)
                    #pragma unroll
                    for (int p = 0; p < 4; p++) acc[r][p] = 0ULL;

                #pragma unroll 5
                for (int k = 0; k < 30; k++) {
                    ull pm[4];
                    #pragma unroll
                    for (int p = 0; p < 4; p++) {
                        unsigned lo = bitf(zb[2*p],   k);
                        unsigned hi = bitf(zb[2*p+1], k);
                        asm("mov.b64 %0,{%1,%2};" : "=l"(pm[p]) : "r"(lo), "r"(hi));
                    }
                    int joff = k * 32 + lane;
                    #pragma unroll
                    for (int r = 0; r < 5; r++) {
                        float w = wr0[r * 9800 + joff];
                        ull wp = pk2(w, w);
                        fma2(acc[r][0], pm[0], wp);
                        fma2(acc[r][1], pm[1], wp);
                        fma2(acc[r][2], pm[2], wp);
                        fma2(acc[r][3], pm[3], wp);
                    }
                }
                {   // k = 30 tail (j = 960 + lane, valid for lane < 20)
                    ull pm[4];
                    #pragma unroll
                    for (int p = 0; p < 4; p++) {
                        unsigned lo = bitf(zb[2*p],   30);
                        unsigned hi = bitf(zb[2*p+1], 30);
                        asm("mov.b64 %0,{%1,%2};" : "=l"(pm[p]) : "r"(lo), "r"(hi));
                    }
                    #pragma unroll
                    for (int r = 0; r < 5; r++) {
                        float w = (lane < 20) ? wr0[r * 9800 + 960 + lane] : 0.f;
                        ull wp = pk2(w, w);
                        fma2(acc[r][0], pm[0], wp);
                        fma2(acc[r][1], pm[1], wp);
                        fma2(acc[r][2], pm[2], wp);
                        fma2(acc[r][3], pm[3], wp);
                    }
                }
                #pragma unroll
                for (int r = 0; r < 5; r++) {
                    float f[8];
                    upk2(acc[r][0], f[0], f[1]); upk2(acc[r][1], f[2], f[3]);
                    upk2(acc[r][2], f[4], f[5]); upk2(acc[r][3], f[6], f[7]);
                    #pragma unroll
                    for (int off = 16; off; off >>= 1) {
                        #pragma unroll
                        for (int s = 0; s < 8; s++)
                            f[s] += __shfl_down_sync(0xffffffffu, f[s], off);
                    }
                    if (lane == 0) {
                        int i = warp + g * 50 + r * 10;
                        #pragma unroll
                        for (int s = 0; s < 8; s++) sm->hs[s][i] = f[s];
                    }
                }
            }

            // ---- pass 1: samples 8..13 (pairs 4..6) ----
            {
                ull acc[5][3];
                #pragma unroll
                for (int r = 0; r < 5; r++)
                    #pragma unroll
                    for (int p = 0; p < 3; p++) acc[r][p] = 0ULL;

                #pragma unroll 5
                for (int k = 0; k < 30; k++) {
                    ull pm[3];
                    #pragma unroll
                    for (int p = 0; p < 3; p++) {
                        unsigned lo = bitf(zb[8+2*p], k);
                        unsigned hi = bitf(zb[9+2*p], k);
                        asm("mov.b64 %0,{%1,%2};" : "=l"(pm[p]) : "r"(lo), "r"(hi));
                    }
                    int joff = k * 32 + lane;
                    #pragma unroll
                    for (int r = 0; r < 5; r++) {
                        float w = wr0[r * 9800 + joff];
                        ull wp = pk2(w, w);
                        fma2(acc[r][0], pm[0], wp);
                        fma2(acc[r][1], pm[1], wp);
                        fma2(acc[r][2], pm[2], wp);
                    }
                }
                {   // k = 30 tail
                    ull pm[3];
                    #pragma unroll
                    for (int p = 0; p < 3; p++) {
                        unsigned lo = bitf(zb[8+2*p], 30);
                        unsigned hi = bitf(zb[9+2*p], 30);
                        asm("mov.b64 %0,{%1,%2};" : "=l"(pm[p]) : "r"(lo), "r"(hi));
                    }
                    #pragma unroll
                    for (int r = 0; r < 5; r++) {
                        float w = (lane < 20) ? wr0[r * 9800 + 960 + lane] : 0.f;
                        ull wp = pk2(w, w);
                        fma2(acc[r][0], pm[0], wp);
                        fma2(acc[r][1], pm[1], wp);
                        fma2(acc[r][2], pm[2], wp);
                    }
                }
                #pragma unroll
                for (int r = 0; r < 5; r++) {
                    float f[6];
                    upk2(acc[r][0], f[0], f[1]); upk2(acc[r][1], f[2], f[3]);
                    upk2(acc[r][2], f[4], f[5]);
                    #pragma unroll
                    for (int off = 16; off; off >>= 1) {
                        #pragma unroll
                        for (int s = 0; s < 6; s++)
                            f[s] += __shfl_down_sync(0xffffffffu, f[s], off);
                    }
                    if (lane == 0) {
                        int i = warp + g * 50 + r * 10;
                        #pragma unroll
                        for (int s = 0; s < 6; s++) sm->hs[8 + s][i] = f[s];
                    }
                }
            }
        }
    }
    __syncthreads();

    // ---- stage A: per-neuron LIF-1 sim -> 32-bit spike train word ----
    for (int idx = t; idx < S * 100; idx += NT) {
        int s = idx / 100, i = idx - s * 100;
        float h = sm->hs[s][i], v = 0.f;
        unsigned word = 0u;
        #pragma unroll
        for (int st = 0; st < NSTEPS; st++) {
            v = v + (h - v) * 0.5f;
            if (v >= 1.0f) { word |= (1u << st); v = 0.f; }
        }
        spkw[s * 104 + i] = word;
    }
    __syncthreads();

    // ---- stage B: Y[s][t][o] = sum_i spike * Wf2  (thread = (s, t=lane)) ----
    for (int s = warp; s < S; s += 10) {
        ull y0 = 0, y1 = 0, y2 = 0, y3 = 0, y4 = 0;
        #pragma unroll 4
        for (int i = 0; i < 100; i++) {
            unsigned wbits = spkw[s * 104 + i];
            unsigned fb = (0u - ((wbits >> lane) & 1u)) & 0x3f800000u;
            ull fp; asm("mov.b64 %0,{%1,%1};" : "=l"(fp) : "r"(fb));
            const ull* wpr = sm->wf2p[i];
            ulonglong2 wA = *(const ulonglong2*)wpr;
            ulonglong2 wB = *(const ulonglong2*)(wpr + 2);
            ull w4 = wpr[4];
            fma2(y0, fp, wA.x); fma2(y1, fp, wA.y);
            fma2(y2, fp, wB.x); fma2(y3, fp, wB.y);
            fma2(y4, fp, w4);
        }
        float yo[10];
        upk2(y0, yo[0], yo[1]); upk2(y1, yo[2], yo[3]);
        upk2(y2, yo[4], yo[5]); upk2(y3, yo[6], yo[7]);
        upk2(y4, yo[8], yo[9]);
        #pragma unroll
        for (int o = 0; o < 10; o++) Y[(s * 10 + o) * 33 + lane] = yo[o];
    }
    __syncthreads();

    // ---- stage C: LIF-2 scan over t, then softmax ----
    if (t < S * 10) {
        int s = t / 10, o = t - (t / 10) * 10;
        float v2 = 0.f, cnt = 0.f;
        const float* yr = &Y[(s * 10 + o) * 33];
        #pragma unroll
        for (int st = 0; st < NSTEPS; st++) {
            float yv = yr[st];
            v2 = v2 + (yv - v2) * 0.5f;
            if (v2 >= 1.0f) { cnt += 1.0f; v2 = 0.f; }
        }
        sm->cnts[s][o] = cnt * (1.0f / 32.0f);
    }
    __syncthreads();

    if (t < S * 10) {
        int s = t / 10, o = t - (t / 10) * 10;
        if (b0 + s < B) {
            float mx = sm->cnts[s][0];
            #pragma unroll
            for (int i = 1; i < 10; i++) mx = fmaxf(mx, sm->cnts[s][i]);
            float ssum = 0.f, mine = 0.f;
            #pragma unroll
            for (int i = 0; i < 10; i++) {
                float e = expf(sm->cnts[s][i] - mx);
                ssum += e;
                if (i == o) mine = e;
            }
            out[(size_t)(b0 + s) * 10 + o] = mine / ssum;
        }
    }
}

extern "C" void kernel_launch(void* const* d_in, const int* in_sizes, int n_in,
                              void* d_out, int out_size) {
    const float* x   = (const float*)d_in[0];
    const float* Wc1 = (const float*)d_in[1];
    const float* Wc2 = (const float*)d_in[2];
    const float* Wf1 = (const float*)d_in[3];
    const float* Wf2 = (const float*)d_in[4];
    float* out = (float*)d_out;
    int B = in_sizes[0] / 784;
    int grid = (B + S - 1) / S;
    size_t smem = sizeof(Smem);
    cudaFuncSetAttribute(snn_fused_kernel,
                         cudaFuncAttributeMaxDynamicSharedMemorySize, (int)smem);
    snn_fused_kernel<<<grid, NT, smem>>>(x, Wc1, Wc2, Wf1, Wf2, out, B);
}